// round 12
// baseline (speedup 1.0000x reference)
#include <cuda_runtime.h>
#include <cstdint>

#define WW 256
#define D4 64            // 256 channels as float4
#define NB 2048
#define TR 8             // tile rows (full width) -> 32 tile-rows
#define RSW 1088         // smem row stride in words = 16 chunks * 68
#define CKW 68           // chunk stride in words (16 cols * 4 + 4 pad)

// 64 MB tile-partial SAT (full-width row prefix, 8-row col prefix) + 8 MB cum.
__device__ float4 g_part[(size_t)256 * WW * D4];
__device__ float4 g_colcum[32 * WW * D4];      // [ti][c][d4], exclusive over ti

__device__ __forceinline__ void acc4(float4& a, const float4 v) {
    a.x += v.x; a.y += v.y; a.z += v.z; a.w += v.w;
}

__device__ __forceinline__ uint32_t smem_u32(const void* p) {
    return (uint32_t)__cvta_generic_to_shared(p);
}

// ---------------------------------------------------------------------------
// Tile SAT: 8 rows x 256 cols (FULL WIDTH) x 4 channels per block,
// 2048 blocks x 128 threads, smem 36864B -> 6 blocks/SM.
// Phase A : thread (r, chunk) cp.asyncs + row-scans 16 cols of its chunk,
//           stores inclusive chunk total to cf[].
// Phase A2: per-thread register prefix of cf -> cf becomes exclusive fix.
// Phase B : thread (c) completes row prefix on the fly (+cf broadcast) and
//           col-scans 8 rows straight out to g_part.
// All smem patterns conflict-free per quarter-warp (CKW=68, RSW=1088).
// ---------------------------------------------------------------------------
__global__ void __launch_bounds__(128, 6) sat_tile(const float4* __restrict__ feat) {
    extern __shared__ float sm[];                 // 8*RSW + 512 words = 36864 B
    float4* cf = reinterpret_cast<float4*>(&sm[TR * RSW]);  // [r][chunk]
    int b    = blockIdx.x;
    int dgrp = b & 63;                            // 64 channel groups (1 float4)
    int ti   = b >> 6;                            // 0..31
    int t    = threadIdx.x;
    int h0   = ti * TR;

    // ---- Phase A: row scan of 16 cols per thread.
    {
        int chunk = t & 15;
        int r     = t >> 4;                       // 0..7
        const float4* __restrict__ src =
            feat + ((size_t)(h0 + r) * WW + chunk * 16) * D4 + dgrp;
        uint32_t sdst = smem_u32(&sm[r * RSW + chunk * CKW]);

#pragma unroll
        for (int g = 0; g < 2; ++g) {
#pragma unroll
            for (int j = 0; j < 8; ++j) {
                int c = g * 8 + j;
                asm volatile("cp.async.cg.shared.global [%0], [%1], 16;\n"
                             :: "r"(sdst + c * 16), "l"(src + (size_t)c * D4)
                             : "memory");
            }
            asm volatile("cp.async.commit_group;\n" ::: "memory");
        }

        float* __restrict__ srow = &sm[r * RSW + chunk * CKW];
        float4 acc = make_float4(0.f, 0.f, 0.f, 0.f);
        float4 buf[8];
#pragma unroll
        for (int g = 0; g < 2; ++g) {
            if (g == 0) asm volatile("cp.async.wait_group 1;\n" ::: "memory");
            else        asm volatile("cp.async.wait_group 0;\n" ::: "memory");
#pragma unroll
            for (int j = 0; j < 8; ++j)
                buf[j] = *reinterpret_cast<const float4*>(&srow[(g * 8 + j) * 4]);
#pragma unroll
            for (int j = 0; j < 8; ++j) {
                acc4(acc, buf[j]);
                *reinterpret_cast<float4*>(&srow[(g * 8 + j) * 4]) = acc;
            }
        }
        cf[r * 16 + chunk] = acc;                 // inclusive chunk total
    }
    __syncthreads();

    // ---- Phase A2: exclusive prefix of chunk totals (register scan).
    {
        int chunk = t & 15;
        int r     = t >> 4;
        float4 fx = make_float4(0.f, 0.f, 0.f, 0.f);
#pragma unroll
        for (int k = 0; k < 15; ++k) {
            float4 v = cf[r * 16 + k];
            if (k < chunk) acc4(fx, v);
        }
        __syncthreads();
        cf[r * 16 + chunk] = fx;                  // now exclusive fix
    }
    __syncthreads();

    // ---- Phase B: complete row prefix + col scan, stream to g_part.
    {
#pragma unroll
        for (int half = 0; half < 2; ++half) {
            int c   = t + half * 128;
            int chk = c >> 4;
            const float* __restrict__ scol = &sm[chk * CKW + (c & 15) * 4];
            float4* __restrict__ dst =
                g_part + ((size_t)h0 * WW + c) * D4 + dgrp;
            float4 acc = make_float4(0.f, 0.f, 0.f, 0.f);
            float4 buf[TR], fbuf[TR];
#pragma unroll
            for (int r = 0; r < TR; ++r) {
                buf[r]  = *reinterpret_cast<const float4*>(&scol[r * RSW]);
                fbuf[r] = cf[r * 16 + chk];       // broadcast within quarter-warp
            }
#pragma unroll
            for (int r = 0; r < TR; ++r) {
                float4 v = buf[r];
                acc4(v, fbuf[r]);
                acc4(acc, v);
                dst[(size_t)r * WW * D4] = acc;
            }
        }
    }
}

// ---------------------------------------------------------------------------
// Fixups: ONLY colcum. thread (c, d4): running register prefix over the 32
// tile-rows' bottom edges (31 independent L2 loads, 32 stores).
// ---------------------------------------------------------------------------
__global__ void __launch_bounds__(256) fixups() {
    int flat = blockIdx.x * 256 + threadIdx.x;    // 16384 threads
    int d4 = flat & 63, c = flat >> 6;
    float4 acc = make_float4(0.f, 0.f, 0.f, 0.f);
#pragma unroll
    for (int s = 0; s < 32; ++s) {
        g_colcum[((size_t)s * WW + c) * D4 + d4] = acc;
        if (s < 31)
            acc4(acc, g_part[((size_t)(s * TR + TR - 1) * WW + c) * D4 + d4]);
    }
}

// Full SAT(r,c) = tile partial (full-width rows) + above-tile-rows cum.
__device__ __forceinline__ float4 satval(int r, int c, int d4) {
    float4 v = g_part[((size_t)r * WW + c) * D4 + d4];
    acc4(v, g_colcum[((size_t)(r >> 3) * WW + c) * D4 + d4]);
    return v;
}

// ---------------------------------------------------------------------------
// Gather: 4 boxes per block, 64 float4 lanes per box, <=8 corner loads (L2).
// ---------------------------------------------------------------------------
__global__ void __launch_bounds__(256) roi_gather(const float* __restrict__ boxes,
                                                  float4* __restrict__ out) {
    int n  = blockIdx.x * 4 + (threadIdx.x >> 6);
    int d4 = threadIdx.x & 63;

    float x1 = boxes[n * 4 + 0];
    float y1 = boxes[n * 4 + 1];
    float x2 = boxes[n * 4 + 2];
    float y2 = boxes[n * 4 + 3];

    // _bounds: lo = max(0, floor(lo_f*256)); hi = rint(hi_f*256 + 0.5)
    //          hi = min(256, max(lo+1, hi)). No FMA contraction (match jax).
    int clo = max(0, (int)floorf(__fmul_rn(x1, 256.0f)));
    int chi = (int)rintf(__fadd_rn(__fmul_rn(x2, 256.0f), 0.5f));
    chi = min(WW, max(clo + 1, chi));

    int rlo = max(0, (int)floorf(__fmul_rn(y1, 256.0f)));
    int rhi = (int)rintf(__fadd_rn(__fmul_rn(y2, 256.0f), 0.5f));
    rhi = min(256, max(rlo + 1, rhi));

    float4 s = satval(rhi - 1, chi - 1, d4);
    if (rlo > 0) {
        float4 a = satval(rlo - 1, chi - 1, d4);
        s.x -= a.x; s.y -= a.y; s.z -= a.z; s.w -= a.w;
    }
    if (clo > 0) {
        float4 bb = satval(rhi - 1, clo - 1, d4);
        s.x -= bb.x; s.y -= bb.y; s.z -= bb.z; s.w -= bb.w;
        if (rlo > 0) acc4(s, satval(rlo - 1, clo - 1, d4));
    }

    float inv = 1.0f / (float)((rhi - rlo) * (chi - clo));
    s.x *= inv; s.y *= inv; s.z *= inv; s.w *= inv;
    out[(size_t)n * D4 + d4] = s;
}

extern "C" void kernel_launch(void* const* d_in, const int* in_sizes, int n_in,
                              void* d_out, int out_size) {
    const float4* feat  = (const float4*)d_in[0];   // (256,256,256) fp32
    const float*  boxes = (const float*)d_in[1];    // (2048,4) fp32
    float4* out = (float4*)d_out;                   // (2048,256) fp32

    const int smem = (TR * RSW + 512) * 4;          // 36864 B -> 6 blocks/SM
    cudaFuncSetAttribute(sat_tile, cudaFuncAttributeMaxDynamicSharedMemorySize, smem);

    sat_tile<<<2048, 128, smem>>>(feat);
    fixups<<<64, 256>>>();                          // 16384 threads
    roi_gather<<<NB / 4, 256>>>(boxes, out);
}

// round 13
// speedup vs baseline: 1.5004x; 1.5004x over previous
#include <cuda_runtime.h>
#include <cstdint>

#define WW 256
#define D4 64            // 256 channels as float4
#define NB 2048
#define RS 528           // smem row stride in words: 528 % 32 == 16
#define TI 16            // tiles: 16 rows x 32 cols -> 16 x 8 tile grid
#define NJOBS 2048       // sat tile jobs
#define SMEMB ((16 * RS + 16 * 4 * 4) * 4)   // 34816 B (< 48KB: no attr needed)

// 64 MB tile-partial SAT + cum tables + barrier state.
__device__ float4 g_part[(size_t)256 * WW * D4];
__device__ float4 g_rowcum[16 * 8 * 16 * D4];  // [ti][tj][r][d4]
__device__ float4 g_colcum[16 * 8 * 32 * D4];  // [ti][tj][c][d4]
__device__ float4 g_blockcum[16 * 8 * D4];     // [ti][tj][d4]
__device__ unsigned g_count = 0;               // barrier arrivals (returns to 0)
__device__ unsigned g_sense = 0;               // monotone epoch counter

__device__ __forceinline__ void acc4(float4& a, const float4 v) {
    a.x += v.x; a.y += v.y; a.z += v.z; a.w += v.w;
}

__device__ __forceinline__ uint32_t smem_u32(const void* p) {
    return (uint32_t)__cvta_generic_to_shared(p);
}

// Grid-wide barrier: all gridDim.x blocks are co-resident (grid sized via the
// occupancy API). Epoch-based so state survives graph replays.
__device__ __forceinline__ void grid_bar(unsigned target) {
    __syncthreads();
    if (threadIdx.x == 0) {
        __threadfence();                              // release my writes
        unsigned my = atomicAdd(&g_count, 1);
        if (my == gridDim.x - 1) {
            g_count = 0;                              // reset for next barrier
            __threadfence();
            atomicAdd(&g_sense, 1);                   // release
        } else {
            while (atomicAdd(&g_sense, 0) < target) __nanosleep(64);
        }
        __threadfence();                              // acquire others' writes
    }
    __syncthreads();
}

// ---------------------------------------------------------------------------
// Persistent fused kernel: phase 1 = tile SATs (R10 geometry: 16x32 pixels x
// 16 channels per job, cp.async staged, conflict-free smem scans), phase 2 =
// fixup tables (register scans), phase 3 = ROI gather. Grid barriers between.
// ---------------------------------------------------------------------------
__global__ void __launch_bounds__(128, 6)
fused(const float4* __restrict__ feat, const float* __restrict__ boxes,
      float4* __restrict__ out) {
    extern __shared__ float sm[];                 // 16*RS + 256 words
    float* carry = &sm[16 * RS];
    int t   = threadIdx.x;
    int kw4 = t & 3;

    __shared__ unsigned s_base;
    if (t == 0) s_base = atomicAdd(&g_sense, 0);  // stable: no increments yet
    __syncthreads();
    unsigned base = s_base;

    uint64_t pol;
    asm volatile("createpolicy.fractional.L2::evict_first.b64 %0, 1.0;" : "=l"(pol));

    // ================= Phase 1: tile SATs =================
    for (int b = blockIdx.x; b < NJOBS; b += gridDim.x) {
        int dgrp = b & 15;
        int tj   = (b >> 4) & 7;
        int ti   = b >> 7;
        int h0 = ti * TI, w0 = tj * 32;
        int c0 = dgrp * 4;

        // Phase A: row scan of 16 columns per thread (cols split by chalf).
        {
            int u     = (t >> 2) & 15;
            int chalf = t >> 6;
            int cb    = chalf * 16;
            const float4* __restrict__ src =
                feat + ((size_t)(h0 + u) * WW + w0 + cb) * D4 + c0 + kw4;
            uint32_t sdst = smem_u32(&sm[u * RS + cb * 16 + kw4 * 4]);

#pragma unroll
            for (int g = 0; g < 2; ++g) {
#pragma unroll
                for (int j = 0; j < 8; ++j) {
                    int c = g * 8 + j;
                    asm volatile(
                        "cp.async.cg.shared.global.L2::cache_hint [%0], [%1], 16, %2;\n"
                        :: "r"(sdst + c * 64), "l"(src + (size_t)c * D4), "l"(pol)
                        : "memory");
                }
                asm volatile("cp.async.commit_group;\n" ::: "memory");
            }

            float* __restrict__ srow = &sm[u * RS + cb * 16 + kw4 * 4];
            float4 acc = make_float4(0.f, 0.f, 0.f, 0.f);
            float4 buf[8];
#pragma unroll
            for (int g = 0; g < 2; ++g) {
                if (g == 0) asm volatile("cp.async.wait_group 1;\n" ::: "memory");
                else        asm volatile("cp.async.wait_group 0;\n" ::: "memory");
#pragma unroll
                for (int j = 0; j < 8; ++j)
                    buf[j] = *reinterpret_cast<const float4*>(&srow[(g * 8 + j) * 16]);
#pragma unroll
                for (int j = 0; j < 8; ++j) {
                    acc4(acc, buf[j]);
                    *reinterpret_cast<float4*>(&srow[(g * 8 + j) * 16]) = acc;
                }
            }
            if (chalf == 0)
                *reinterpret_cast<float4*>(&carry[(u * 4 + kw4) * 4]) = acc;
        }
        __syncthreads();

        // Phase B: col scan of 16 rows per thread (one column each).
        {
            int c = t >> 2;
            bool needc = (c >= 16);
            const float* __restrict__ scol = &sm[c * 16 + kw4 * 4];
            const float* __restrict__ carr = &carry[kw4 * 4];
            float4* __restrict__ dst =
                g_part + ((size_t)h0 * WW + w0 + c) * D4 + c0 + kw4;
            float4 acc = make_float4(0.f, 0.f, 0.f, 0.f);
            float4 buf[8], cbuf[8];
#pragma unroll
            for (int rr = 0; rr < 16; rr += 8) {
#pragma unroll
                for (int j = 0; j < 8; ++j) {
                    buf[j]  = *reinterpret_cast<const float4*>(&scol[(rr + j) * RS]);
                    cbuf[j] = *reinterpret_cast<const float4*>(&carr[(rr + j) * 16]);
                }
#pragma unroll
                for (int j = 0; j < 8; ++j) {
                    float4 v = buf[j];
                    if (needc) acc4(v, cbuf[j]);
                    acc4(acc, v);
                    dst[(size_t)(rr + j) * WW * D4] = acc;
                }
            }
        }
        __syncthreads();                         // smem reused by next job
    }

    grid_bar(base + 1);

    // ================= Phase 2: fixup tables =================
    for (int flat = blockIdx.x * 128 + t; flat < 33280; flat += gridDim.x * 128) {
        if (flat < 16384) {                        // rowcum
            int d4 = flat & 63, r = (flat >> 6) & 15, ti = flat >> 10;
            float4 e[7];
#pragma unroll
            for (int s = 0; s < 7; ++s)
                e[s] = g_part[((size_t)(ti * TI + r) * WW + s * 32 + 31) * D4 + d4];
            float4 acc = make_float4(0.f, 0.f, 0.f, 0.f);
#pragma unroll
            for (int tj = 0; tj < 8; ++tj) {
                g_rowcum[((ti * 8 + tj) * 16 + r) * 64 + d4] = acc;
                if (tj < 7) acc4(acc, e[tj]);
            }
        } else if (flat < 32768) {                 // colcum
            int f = flat - 16384;
            int d4 = f & 63, c = (f >> 6) & 31, tj = f >> 11;
            float4 e[15];
#pragma unroll
            for (int s = 0; s < 15; ++s)
                e[s] = g_part[((size_t)(s * TI + 15) * WW + tj * 32 + c) * D4 + d4];
            float4 acc = make_float4(0.f, 0.f, 0.f, 0.f);
#pragma unroll
            for (int ti = 0; ti < 16; ++ti) {
                g_colcum[((ti * 8 + tj) * 32 + c) * 64 + d4] = acc;
                if (ti < 15) acc4(acc, e[ti]);
            }
        } else {                                   // blockcum
            int f = flat - 32768;
            int d4 = f & 63, tj = f >> 6;
            float4 acc = make_float4(0.f, 0.f, 0.f, 0.f);
#pragma unroll
            for (int ti = 0; ti < 16; ++ti) {
                g_blockcum[(ti * 8 + tj) * 64 + d4] = acc;
                float4 e[7];
#pragma unroll
                for (int s = 0; s < 7; ++s)
                    e[s] = g_part[((size_t)(ti * TI + 15) * WW + s * 32 + 31) * D4 + d4];
#pragma unroll
                for (int s = 0; s < 7; ++s)
                    if (s < tj) acc4(acc, e[s]);
            }
        }
    }

    grid_bar(base + 2);

    // ================= Phase 3: ROI gather =================
    for (int i = blockIdx.x * 128 + t; i < NB * 64; i += gridDim.x * 128) {
        int n = i >> 6, d4 = i & 63;

        float x1 = boxes[n * 4 + 0];
        float y1 = boxes[n * 4 + 1];
        float x2 = boxes[n * 4 + 2];
        float y2 = boxes[n * 4 + 3];

        // _bounds: lo = max(0, floor(lo_f*256)); hi = rint(hi_f*256 + 0.5)
        //          hi = min(256, max(lo+1, hi)). No FMA contraction (match jax).
        int clo = max(0, (int)floorf(__fmul_rn(x1, 256.0f)));
        int chi = (int)rintf(__fadd_rn(__fmul_rn(x2, 256.0f), 0.5f));
        chi = min(WW, max(clo + 1, chi));

        int rlo = max(0, (int)floorf(__fmul_rn(y1, 256.0f)));
        int rhi = (int)rintf(__fadd_rn(__fmul_rn(y2, 256.0f), 0.5f));
        rhi = min(256, max(rlo + 1, rhi));

        auto satval = [&](int r, int c) {
            int ti = r >> 4, tj = c >> 5;
            float4 v = g_part[((size_t)r * WW + c) * D4 + d4];
            acc4(v, g_rowcum[((ti * 8 + tj) * 16 + (r & 15)) * 64 + d4]);
            acc4(v, g_colcum[((ti * 8 + tj) * 32 + (c & 31)) * 64 + d4]);
            acc4(v, g_blockcum[(ti * 8 + tj) * 64 + d4]);
            return v;
        };

        float4 s = satval(rhi - 1, chi - 1);
        if (rlo > 0) {
            float4 a = satval(rlo - 1, chi - 1);
            s.x -= a.x; s.y -= a.y; s.z -= a.z; s.w -= a.w;
        }
        if (clo > 0) {
            float4 bb = satval(rhi - 1, clo - 1);
            s.x -= bb.x; s.y -= bb.y; s.z -= bb.z; s.w -= bb.w;
            if (rlo > 0) acc4(s, satval(rlo - 1, clo - 1));
        }

        float inv = 1.0f / (float)((rhi - rlo) * (chi - clo));
        s.x *= inv; s.y *= inv; s.z *= inv; s.w *= inv;
        out[(size_t)n * D4 + d4] = s;
    }
}

extern "C" void kernel_launch(void* const* d_in, const int* in_sizes, int n_in,
                              void* d_out, int out_size) {
    const float4* feat  = (const float4*)d_in[0];   // (256,256,256) fp32
    const float*  boxes = (const float*)d_in[1];    // (2048,4) fp32
    float4* out = (float4*)d_out;                   // (2048,256) fp32

    // Size the grid to guaranteed co-residency (required by grid_bar).
    int dev = 0, sms = 0, perSM = 0;
    cudaGetDevice(&dev);
    cudaDeviceGetAttribute(&sms, cudaDevAttrMultiProcessorCount, dev);
    cudaOccupancyMaxActiveBlocksPerMultiprocessor(&perSM, fused, 128, SMEMB);
    int grid = sms * perSM;
    if (grid > NJOBS) grid = NJOBS;
    if (grid < 1) grid = 1;

    fused<<<grid, 128, SMEMB>>>(feat, boxes, out);
}

// round 14
// speedup vs baseline: 1.7232x; 1.1485x over previous
#include <cuda_runtime.h>
#include <cstdint>

#define WW 256
#define D4 64            // 256 channels as float4
#define NB 2048
#define RS 528           // smem row stride in words: 528 % 32 == 16
#define TI 16            // tiles: 16 rows x 32 cols -> 16 x 8 tile grid

// 64 MB tile-partial SAT + cum tables.
__device__ float4 g_part[(size_t)256 * WW * D4];
__device__ float4 g_rowcum[16 * 8 * 16 * D4];  // [ti][tj][r][d4]
__device__ float4 g_colcum[16 * 8 * 32 * D4];  // [ti][tj][c][d4]
__device__ float4 g_blockcum[16 * 8 * D4];     // [ti][tj][d4]

__device__ __forceinline__ void acc4(float4& a, const float4 v) {
    a.x += v.x; a.y += v.y; a.z += v.z; a.w += v.w;
}

__device__ __forceinline__ uint32_t smem_u32(const void* p) {
    return (uint32_t)__cvta_generic_to_shared(p);
}

// ---------------------------------------------------------------------------
// Tile SAT (R11 geometry, best measured): 16x32 pixels x 16 channels per
// block, 2048 blocks x 128 threads, smem 34.8KB -> 6 blocks/SM.
// cp.async staged (evict_first), conflict-free smem scans.
// ---------------------------------------------------------------------------
__global__ void __launch_bounds__(128, 6) sat_tile(const float4* __restrict__ feat) {
    extern __shared__ float sm[];                 // 16*RS + 256 words = 34816 B
    float* carry = &sm[16 * RS];                  // [r][kw4] float4: 1KB
    int b     = blockIdx.x;
    int dgrp  = b & 15;
    int tj    = (b >> 4) & 7;
    int ti    = b >> 7;
    int t     = threadIdx.x;
    int kw4   = t & 3;
    int h0 = ti * TI, w0 = tj * 32;
    int c0 = dgrp * 4;

    uint64_t pol;
    asm volatile("createpolicy.fractional.L2::evict_first.b64 %0, 1.0;" : "=l"(pol));

    // ---- Phase A: row scan of 16 columns per thread (cols split by chalf).
    {
        int u     = (t >> 2) & 15;
        int chalf = t >> 6;
        int cb    = chalf * 16;
        const float4* __restrict__ src =
            feat + ((size_t)(h0 + u) * WW + w0 + cb) * D4 + c0 + kw4;
        uint32_t sdst = smem_u32(&sm[u * RS + cb * 16 + kw4 * 4]);

#pragma unroll
        for (int g = 0; g < 2; ++g) {
#pragma unroll
            for (int j = 0; j < 8; ++j) {
                int c = g * 8 + j;
                asm volatile(
                    "cp.async.cg.shared.global.L2::cache_hint [%0], [%1], 16, %2;\n"
                    :: "r"(sdst + c * 64), "l"(src + (size_t)c * D4), "l"(pol)
                    : "memory");
            }
            asm volatile("cp.async.commit_group;\n" ::: "memory");
        }

        float* __restrict__ srow = &sm[u * RS + cb * 16 + kw4 * 4];
        float4 acc = make_float4(0.f, 0.f, 0.f, 0.f);
        float4 buf[8];
#pragma unroll
        for (int g = 0; g < 2; ++g) {
            if (g == 0) asm volatile("cp.async.wait_group 1;\n" ::: "memory");
            else        asm volatile("cp.async.wait_group 0;\n" ::: "memory");
#pragma unroll
            for (int j = 0; j < 8; ++j)
                buf[j] = *reinterpret_cast<const float4*>(&srow[(g * 8 + j) * 16]);
#pragma unroll
            for (int j = 0; j < 8; ++j) {
                acc4(acc, buf[j]);
                *reinterpret_cast<float4*>(&srow[(g * 8 + j) * 16]) = acc;
            }
        }
        if (chalf == 0)
            *reinterpret_cast<float4*>(&carry[(u * 4 + kw4) * 4]) = acc;
    }
    __syncthreads();

    // ---- Phase B: col scan of 16 rows per thread (one column each).
    {
        int c = t >> 2;
        bool needc = (c >= 16);
        const float* __restrict__ scol = &sm[c * 16 + kw4 * 4];
        const float* __restrict__ carr = &carry[kw4 * 4];
        float4* __restrict__ dst =
            g_part + ((size_t)h0 * WW + w0 + c) * D4 + c0 + kw4;
        float4 acc = make_float4(0.f, 0.f, 0.f, 0.f);
        float4 buf[8], cbuf[8];
#pragma unroll
        for (int rr = 0; rr < 16; rr += 8) {
#pragma unroll
            for (int j = 0; j < 8; ++j) {
                buf[j]  = *reinterpret_cast<const float4*>(&scol[(rr + j) * RS]);
                cbuf[j] = *reinterpret_cast<const float4*>(&carr[(rr + j) * 16]);
            }
#pragma unroll
            for (int j = 0; j < 8; ++j) {
                float4 v = buf[j];
                if (needc) acc4(v, cbuf[j]);
                acc4(acc, v);
                dst[(size_t)(rr + j) * WW * D4] = acc;
            }
        }
    }
}

// ---------------------------------------------------------------------------
// Fixups, all sections fully parallel (40960 threads, 160 blocks):
//   [0, 16384)      rowcum:   thread (ti, r, d4), 7 edge loads, scan tj
//   [16384, 32768)  colcum:   thread (tj, c, d4), 15 edge loads, scan ti
//   [32768, 40960)  blockcum: thread (ti, tj, d4), <=105 predicated
//                   INDEPENDENT loads -> one L2-latency round, no serial scan.
// ---------------------------------------------------------------------------
__global__ void __launch_bounds__(256) fixups() {
    int flat = blockIdx.x * 256 + threadIdx.x;
    if (flat < 16384) {                        // rowcum
        int d4 = flat & 63, r = (flat >> 6) & 15, ti = flat >> 10;
        float4 e[7];
#pragma unroll
        for (int s = 0; s < 7; ++s)
            e[s] = g_part[((size_t)(ti * TI + r) * WW + s * 32 + 31) * D4 + d4];
        float4 acc = make_float4(0.f, 0.f, 0.f, 0.f);
#pragma unroll
        for (int tj = 0; tj < 8; ++tj) {
            g_rowcum[((ti * 8 + tj) * 16 + r) * 64 + d4] = acc;
            if (tj < 7) acc4(acc, e[tj]);
        }
    } else if (flat < 32768) {                 // colcum
        int f = flat - 16384;
        int d4 = f & 63, c = (f >> 6) & 31, tj = f >> 11;
        float4 e[15];
#pragma unroll
        for (int s = 0; s < 15; ++s)
            e[s] = g_part[((size_t)(s * TI + 15) * WW + tj * 32 + c) * D4 + d4];
        float4 acc = make_float4(0.f, 0.f, 0.f, 0.f);
#pragma unroll
        for (int ti = 0; ti < 16; ++ti) {
            g_colcum[((ti * 8 + tj) * 32 + c) * 64 + d4] = acc;
            if (ti < 15) acc4(acc, e[ti]);
        }
    } else if (flat < 40960) {                 // blockcum, one thread per entry
        int f = flat - 32768;
        int d4 = f & 63, tj = (f >> 6) & 7, ti = f >> 9;
        float4 acc = make_float4(0.f, 0.f, 0.f, 0.f);
#pragma unroll
        for (int si = 0; si < 15; ++si)
#pragma unroll
            for (int sj = 0; sj < 7; ++sj)
                if (si < ti && sj < tj)
                    acc4(acc, g_part[((size_t)(si * TI + 15) * WW + sj * 32 + 31) * D4 + d4]);
        g_blockcum[(ti * 8 + tj) * 64 + d4] = acc;
    }
}

// Full SAT(r,c) = tile partial + left strip + above strip + above-left blocks.
__device__ __forceinline__ float4 satval(int r, int c, int d4) {
    int ti = r >> 4, tj = c >> 5;
    float4 v = g_part[((size_t)r * WW + c) * D4 + d4];
    acc4(v, g_rowcum[((ti * 8 + tj) * 16 + (r & 15)) * 64 + d4]);
    acc4(v, g_colcum[((ti * 8 + tj) * 32 + (c & 31)) * 64 + d4]);
    acc4(v, g_blockcum[(ti * 8 + tj) * 64 + d4]);
    return v;
}

// ---------------------------------------------------------------------------
// Gather: branch-free. All 4 corners loaded unconditionally (clamped
// indices) -> 16 independent L2 loads per thread, combined with 0/1 weights.
// ---------------------------------------------------------------------------
__global__ void __launch_bounds__(256) roi_gather(const float* __restrict__ boxes,
                                                  float4* __restrict__ out) {
    int n  = blockIdx.x * 4 + (threadIdx.x >> 6);
    int d4 = threadIdx.x & 63;

    float x1 = boxes[n * 4 + 0];
    float y1 = boxes[n * 4 + 1];
    float x2 = boxes[n * 4 + 2];
    float y2 = boxes[n * 4 + 3];

    // _bounds: lo = max(0, floor(lo_f*256)); hi = rint(hi_f*256 + 0.5)
    //          hi = min(256, max(lo+1, hi)). No FMA contraction (match jax).
    int clo = max(0, (int)floorf(__fmul_rn(x1, 256.0f)));
    int chi = (int)rintf(__fadd_rn(__fmul_rn(x2, 256.0f), 0.5f));
    chi = min(WW, max(clo + 1, chi));

    int rlo = max(0, (int)floorf(__fmul_rn(y1, 256.0f)));
    int rhi = (int)rintf(__fadd_rn(__fmul_rn(y2, 256.0f), 0.5f));
    rhi = min(256, max(rlo + 1, rhi));

    int r2 = rhi - 1, c2 = chi - 1;
    int r1 = max(rlo - 1, 0), c1 = max(clo - 1, 0);
    float wr = (rlo > 0) ? 1.0f : 0.0f;
    float wc = (clo > 0) ? 1.0f : 0.0f;
    float wrc = wr * wc;

    float4 A = satval(r2, c2, d4);
    float4 B = satval(r1, c2, d4);
    float4 C = satval(r2, c1, d4);
    float4 D = satval(r1, c1, d4);

    float inv = 1.0f / (float)((rhi - rlo) * (chi - clo));
    float4 s;
    s.x = (A.x - wr * B.x - wc * C.x + wrc * D.x) * inv;
    s.y = (A.y - wr * B.y - wc * C.y + wrc * D.y) * inv;
    s.z = (A.z - wr * B.z - wc * C.z + wrc * D.z) * inv;
    s.w = (A.w - wr * B.w - wc * C.w + wrc * D.w) * inv;
    out[(size_t)n * D4 + d4] = s;
}

extern "C" void kernel_launch(void* const* d_in, const int* in_sizes, int n_in,
                              void* d_out, int out_size) {
    const float4* feat  = (const float4*)d_in[0];   // (256,256,256) fp32
    const float*  boxes = (const float*)d_in[1];    // (2048,4) fp32
    float4* out = (float4*)d_out;                   // (2048,256) fp32

    const int smem = (16 * RS + 16 * 4 * 4) * 4;    // 34816 B -> 6 blocks/SM
    cudaFuncSetAttribute(sat_tile, cudaFuncAttributeMaxDynamicSharedMemorySize, smem);

    sat_tile<<<2048, 128, smem>>>(feat);
    fixups<<<160, 256>>>();                         // 40960 threads
    roi_gather<<<NB / 4, 256>>>(boxes, out);
}

// round 15
// speedup vs baseline: 1.7344x; 1.0065x over previous
#include <cuda_runtime.h>
#include <cstdint>

#define WW 256
#define D4 64            // 256 channels as float4
#define NB 2048
#define RS 528           // smem row stride in words: 528 % 32 == 16
#define TI 16            // tiles: 16 rows x 32 cols -> 16 x 8 tile grid

// 64 MB tile-partial SAT + cum tables.
__device__ float4 g_part[(size_t)256 * WW * D4];
__device__ float4 g_rowcum[16 * 8 * 16 * D4];  // [ti][tj][r][d4]
__device__ float4 g_colcum[16 * 8 * 32 * D4];  // [ti][tj][c][d4]
__device__ float4 g_blockcum[16 * 8 * D4];     // [ti][tj][d4]

__device__ __forceinline__ void acc4(float4& a, const float4 v) {
    a.x += v.x; a.y += v.y; a.z += v.z; a.w += v.w;
}

__device__ __forceinline__ uint32_t smem_u32(const void* p) {
    return (uint32_t)__cvta_generic_to_shared(p);
}

// ---------------------------------------------------------------------------
// Tile SAT (R11 geometry, best measured): 16x32 pixels x 16 channels per
// block, 2048 blocks x 128 threads, smem 34.8KB -> 6 blocks/SM.
// cp.async staged (evict_first), conflict-free smem scans.
// ---------------------------------------------------------------------------
__global__ void __launch_bounds__(128, 6) sat_tile(const float4* __restrict__ feat) {
    extern __shared__ float sm[];                 // 16*RS + 256 words = 34816 B
    float* carry = &sm[16 * RS];                  // [r][kw4] float4: 1KB
    int b     = blockIdx.x;
    int dgrp  = b & 15;
    int tj    = (b >> 4) & 7;
    int ti    = b >> 7;
    int t     = threadIdx.x;
    int kw4   = t & 3;
    int h0 = ti * TI, w0 = tj * 32;
    int c0 = dgrp * 4;

    uint64_t pol;
    asm volatile("createpolicy.fractional.L2::evict_first.b64 %0, 1.0;" : "=l"(pol));

    // ---- Phase A: row scan of 16 columns per thread (cols split by chalf).
    {
        int u     = (t >> 2) & 15;
        int chalf = t >> 6;
        int cb    = chalf * 16;
        const float4* __restrict__ src =
            feat + ((size_t)(h0 + u) * WW + w0 + cb) * D4 + c0 + kw4;
        uint32_t sdst = smem_u32(&sm[u * RS + cb * 16 + kw4 * 4]);

#pragma unroll
        for (int g = 0; g < 2; ++g) {
#pragma unroll
            for (int j = 0; j < 8; ++j) {
                int c = g * 8 + j;
                asm volatile(
                    "cp.async.cg.shared.global.L2::cache_hint [%0], [%1], 16, %2;\n"
                    :: "r"(sdst + c * 64), "l"(src + (size_t)c * D4), "l"(pol)
                    : "memory");
            }
            asm volatile("cp.async.commit_group;\n" ::: "memory");
        }

        float* __restrict__ srow = &sm[u * RS + cb * 16 + kw4 * 4];
        float4 acc = make_float4(0.f, 0.f, 0.f, 0.f);
        float4 buf[8];
#pragma unroll
        for (int g = 0; g < 2; ++g) {
            if (g == 0) asm volatile("cp.async.wait_group 1;\n" ::: "memory");
            else        asm volatile("cp.async.wait_group 0;\n" ::: "memory");
#pragma unroll
            for (int j = 0; j < 8; ++j)
                buf[j] = *reinterpret_cast<const float4*>(&srow[(g * 8 + j) * 16]);
#pragma unroll
            for (int j = 0; j < 8; ++j) {
                acc4(acc, buf[j]);
                *reinterpret_cast<float4*>(&srow[(g * 8 + j) * 16]) = acc;
            }
        }
        if (chalf == 0)
            *reinterpret_cast<float4*>(&carry[(u * 4 + kw4) * 4]) = acc;
    }
    __syncthreads();

    // ---- Phase B: col scan of 16 rows per thread (one column each).
    {
        int c = t >> 2;
        bool needc = (c >= 16);
        const float* __restrict__ scol = &sm[c * 16 + kw4 * 4];
        const float* __restrict__ carr = &carry[kw4 * 4];
        float4* __restrict__ dst =
            g_part + ((size_t)h0 * WW + w0 + c) * D4 + c0 + kw4;
        float4 acc = make_float4(0.f, 0.f, 0.f, 0.f);
        float4 buf[8], cbuf[8];
#pragma unroll
        for (int rr = 0; rr < 16; rr += 8) {
#pragma unroll
            for (int j = 0; j < 8; ++j) {
                buf[j]  = *reinterpret_cast<const float4*>(&scol[(rr + j) * RS]);
                cbuf[j] = *reinterpret_cast<const float4*>(&carr[(rr + j) * 16]);
            }
#pragma unroll
            for (int j = 0; j < 8; ++j) {
                float4 v = buf[j];
                if (needc) acc4(v, cbuf[j]);
                acc4(acc, v);
                dst[(size_t)(rr + j) * WW * D4] = acc;
            }
        }
    }
}

// ---------------------------------------------------------------------------
// Fixups (40960 threads, 160 blocks):
//   [0, 16384)      rowcum:   thread (ti, r, d4), 7 edge loads, scan tj
//   [16384, 32768)  colcum:   thread (tj, c, d4), 15 edge loads, scan ti
//   [32768, 40960)  blockcum: thread (ti, tj, d4), <=105 predicated
//                   INDEPENDENT loads -> one L2-latency round (no serial scan)
// ---------------------------------------------------------------------------
__global__ void __launch_bounds__(256) fixups() {
    int flat = blockIdx.x * 256 + threadIdx.x;
    if (flat < 16384) {                        // rowcum
        int d4 = flat & 63, r = (flat >> 6) & 15, ti = flat >> 10;
        float4 e[7];
#pragma unroll
        for (int s = 0; s < 7; ++s)
            e[s] = g_part[((size_t)(ti * TI + r) * WW + s * 32 + 31) * D4 + d4];
        float4 acc = make_float4(0.f, 0.f, 0.f, 0.f);
#pragma unroll
        for (int tj = 0; tj < 8; ++tj) {
            g_rowcum[((ti * 8 + tj) * 16 + r) * 64 + d4] = acc;
            if (tj < 7) acc4(acc, e[tj]);
        }
    } else if (flat < 32768) {                 // colcum
        int f = flat - 16384;
        int d4 = f & 63, c = (f >> 6) & 31, tj = f >> 11;
        float4 e[15];
#pragma unroll
        for (int s = 0; s < 15; ++s)
            e[s] = g_part[((size_t)(s * TI + 15) * WW + tj * 32 + c) * D4 + d4];
        float4 acc = make_float4(0.f, 0.f, 0.f, 0.f);
#pragma unroll
        for (int ti = 0; ti < 16; ++ti) {
            g_colcum[((ti * 8 + tj) * 32 + c) * 64 + d4] = acc;
            if (ti < 15) acc4(acc, e[ti]);
        }
    } else if (flat < 40960) {                 // blockcum, one thread per entry
        int f = flat - 32768;
        int d4 = f & 63, tj = (f >> 6) & 7, ti = f >> 9;
        float4 acc = make_float4(0.f, 0.f, 0.f, 0.f);
#pragma unroll
        for (int si = 0; si < 15; ++si)
#pragma unroll
            for (int sj = 0; sj < 7; ++sj)
                if (si < ti && sj < tj)
                    acc4(acc, g_part[((size_t)(si * TI + 15) * WW + sj * 32 + 31) * D4 + d4]);
        g_blockcum[(ti * 8 + tj) * 64 + d4] = acc;
    }
}

// Full SAT(r,c) = tile partial + left strip + above strip + above-left blocks.
__device__ __forceinline__ float4 satval(int r, int c, int d4) {
    int ti = r >> 4, tj = c >> 5;
    float4 v = g_part[((size_t)r * WW + c) * D4 + d4];
    acc4(v, g_rowcum[((ti * 8 + tj) * 16 + (r & 15)) * 64 + d4]);
    acc4(v, g_colcum[((ti * 8 + tj) * 32 + (c & 31)) * 64 + d4]);
    acc4(v, g_blockcum[(ti * 8 + tj) * 64 + d4]);
    return v;
}

// ---------------------------------------------------------------------------
// Gather (R11 conditional form — measured faster than branch-free):
// 4 boxes per block, 64 float4 lanes per box, <=16 corner loads (L2).
// ---------------------------------------------------------------------------
__global__ void __launch_bounds__(256) roi_gather(const float* __restrict__ boxes,
                                                  float4* __restrict__ out) {
    int n  = blockIdx.x * 4 + (threadIdx.x >> 6);
    int d4 = threadIdx.x & 63;

    float x1 = boxes[n * 4 + 0];
    float y1 = boxes[n * 4 + 1];
    float x2 = boxes[n * 4 + 2];
    float y2 = boxes[n * 4 + 3];

    // _bounds: lo = max(0, floor(lo_f*256)); hi = rint(hi_f*256 + 0.5)
    //          hi = min(256, max(lo+1, hi)). No FMA contraction (match jax).
    int clo = max(0, (int)floorf(__fmul_rn(x1, 256.0f)));
    int chi = (int)rintf(__fadd_rn(__fmul_rn(x2, 256.0f), 0.5f));
    chi = min(WW, max(clo + 1, chi));

    int rlo = max(0, (int)floorf(__fmul_rn(y1, 256.0f)));
    int rhi = (int)rintf(__fadd_rn(__fmul_rn(y2, 256.0f), 0.5f));
    rhi = min(256, max(rlo + 1, rhi));

    float4 s = satval(rhi - 1, chi - 1, d4);
    if (rlo > 0) {
        float4 a = satval(rlo - 1, chi - 1, d4);
        s.x -= a.x; s.y -= a.y; s.z -= a.z; s.w -= a.w;
    }
    if (clo > 0) {
        float4 bb = satval(rhi - 1, clo - 1, d4);
        s.x -= bb.x; s.y -= bb.y; s.z -= bb.z; s.w -= bb.w;
        if (rlo > 0) acc4(s, satval(rlo - 1, clo - 1, d4));
    }

    float inv = 1.0f / (float)((rhi - rlo) * (chi - clo));
    s.x *= inv; s.y *= inv; s.z *= inv; s.w *= inv;
    out[(size_t)n * D4 + d4] = s;
}

extern "C" void kernel_launch(void* const* d_in, const int* in_sizes, int n_in,
                              void* d_out, int out_size) {
    const float4* feat  = (const float4*)d_in[0];   // (256,256,256) fp32
    const float*  boxes = (const float*)d_in[1];    // (2048,4) fp32
    float4* out = (float4*)d_out;                   // (2048,256) fp32

    const int smem = (16 * RS + 16 * 4 * 4) * 4;    // 34816 B -> 6 blocks/SM
    cudaFuncSetAttribute(sat_tile, cudaFuncAttributeMaxDynamicSharedMemorySize, smem);

    sat_tile<<<2048, 128, smem>>>(feat);
    fixups<<<160, 256>>>();                         // 40960 threads
    roi_gather<<<NB / 4, 256>>>(boxes, out);
}